// round 1
// baseline (speedup 1.0000x reference)
#include <cuda_runtime.h>
#include <math.h>

#define BB 64
#define TT 2048
#define DIM 256
#define VOCAB 32000
#define NT 2
#define EPS_CUT 1e-9f

// Scratch (static __device__ globals: no allocation)
__device__ float d_p[VOCAB];      // emb[v] . Wg
__device__ float d_w[BB * TT];    // per-step weight (1-g)*suffixprod
__device__ int   d_t0[BB];        // cutoff index per batch
__device__ float d_hT[BB * DIM];  // final hidden state

// ---------------------------------------------------------------------------
// K1: p[v] = dot(emb[v], Wg)   (one warp per vocab row)
// ---------------------------------------------------------------------------
__global__ void k_vocab_gate(const float* __restrict__ emb,
                             const float* __restrict__ Wg) {
    int warp = (blockIdx.x * blockDim.x + threadIdx.x) >> 5;
    int lane = threadIdx.x & 31;
    if (warp >= VOCAB) return;
    const float4* e4 = (const float4*)(emb + (size_t)warp * DIM);
    const float4* w4 = (const float4*)Wg;
    float4 a0 = e4[lane], a1 = e4[lane + 32];
    float4 b0 = w4[lane], b1 = w4[lane + 32];
    float s = a0.x * b0.x + a0.y * b0.y + a0.z * b0.z + a0.w * b0.w
            + a1.x * b1.x + a1.y * b1.y + a1.z * b1.z + a1.w * b1.w;
#pragma unroll
    for (int off = 16; off; off >>= 1)
        s += __shfl_xor_sync(0xffffffffu, s, off);
    if (lane == 0) d_p[warp] = s;
}

// ---------------------------------------------------------------------------
// K2: per-batch suffix-product scan.
//   g_t = sigmoid(p[x[b,t]] + Wg_b)
//   S_t = prod_{s>t} g_s   (non-decreasing in t)
//   w_t = (1-g_t) * S_t
//   t0  = min t with S_t >= EPS_CUT  (S_{T-1}=1 so always exists)
// Also zeroes d_hT.
// One block per b, 256 threads, 8 timesteps per thread.
// ---------------------------------------------------------------------------
__global__ void k_scan(const int* __restrict__ x,
                       const float* __restrict__ Wg_b) {
    int b = blockIdx.x;
    int tid = threadIdx.x;
    float gb = Wg_b[0];

    __shared__ float sm[256];
    __shared__ int s_t0;
    if (tid == 0) s_t0 = TT;

    float gl[8], sl[8];
    int tb = tid * 8;
    float cum = 1.f;
#pragma unroll
    for (int j = 7; j >= 0; j--) {
        int xv = x[b * TT + tb + j];
        float z = d_p[xv] + gb;
        float g = 1.f / (1.f + expf(-z));
        gl[j] = g;
        sl[j] = cum;   // product of g's AFTER j within this chunk
        cum *= g;
    }
    sm[tid] = cum;     // chunk product
    __syncthreads();
    // inclusive suffix product over chunk products
#pragma unroll
    for (int off = 1; off < 256; off <<= 1) {
        float v = (tid + off < 256) ? sm[tid + off] : 1.f;
        __syncthreads();
        sm[tid] *= v;
        __syncthreads();
    }
    float Q = (tid < 255) ? sm[tid + 1] : 1.f;  // product of later chunks

    int myt0 = TT;
#pragma unroll
    for (int j = 0; j < 8; j++) {
        float S = Q * sl[j];
        d_w[b * TT + tb + j] = (1.f - gl[j]) * S;
        int t = tb + j;
        if (S >= EPS_CUT && t < myt0) myt0 = t;
    }
    atomicMin(&s_t0, myt0);
    d_hT[b * DIM + tid] = 0.f;
    __syncthreads();
    if (tid == 0) d_t0[b] = s_t0;
}

// ---------------------------------------------------------------------------
// K3: hT[b,:] += sum_{t>=t0} w_t * tanh(W @ emb[x[b,t]] + Wb)
// grid (dhalf=2, chunk=NT, b=64), 512 threads.
//   thread: d = tid&127 (local output dim), kq = tid>>7 (k-quarter 0..3)
//   W row quarter (64 floats) lives in REGISTERS; e row in double-buffered smem.
// ---------------------------------------------------------------------------
__global__ void __launch_bounds__(512, 2) k_main(
        const int* __restrict__ x, const float* __restrict__ emb,
        const float* __restrict__ W, const float* __restrict__ Wb) {
    int dh = blockIdx.x;
    int chunk = blockIdx.y;
    int b = blockIdx.z;
    int tid = threadIdx.x;
    int d = tid & 127;
    int kq = tid >> 7;
    int dg = dh * 128 + d;

    // Load this thread's 64 W values into registers
    float wreg[64];
    const float4* W4 = (const float4*)(W + (size_t)dg * DIM + kq * 64);
#pragma unroll
    for (int i = 0; i < 16; i++) {
        float4 v = W4[i];
        wreg[4 * i + 0] = v.x; wreg[4 * i + 1] = v.y;
        wreg[4 * i + 2] = v.z; wreg[4 * i + 3] = v.w;
    }
    float wb = Wb[dg];
    int t0 = d_t0[b];

    __shared__ float e_s[2][DIM];
    __shared__ float part[3][128];

    float acc = 0.f;
    int tstart = TT - 1 - chunk;
    int cur = 0;
    if (tstart >= t0 && tid < DIM) {
        int xv = x[b * TT + tstart];
        e_s[0][tid] = emb[(size_t)xv * DIM + tid];
    }
    __syncthreads();

    for (int t = tstart; t >= t0; t -= NT) {
        // prefetch next e row into registers (hides L2 latency)
        float enext = 0.f;
        int tn = t - NT;
        bool havenext = (tn >= t0);
        if (havenext && tid < DIM) {
            int xv = x[b * TT + tn];
            enext = emb[(size_t)xv * DIM + tid];
        }
        // partial dot over this thread's 64 k's
        const float4* ev = (const float4*)(&e_s[cur][kq * 64]);
        float s0 = 0.f, s1 = 0.f, s2 = 0.f, s3 = 0.f;
#pragma unroll
        for (int i = 0; i < 16; i++) {
            float4 e4 = ev[i];
            s0 = fmaf(wreg[4 * i + 0], e4.x, s0);
            s1 = fmaf(wreg[4 * i + 1], e4.y, s1);
            s2 = fmaf(wreg[4 * i + 2], e4.z, s2);
            s3 = fmaf(wreg[4 * i + 3], e4.w, s3);
        }
        float ps = (s0 + s1) + (s2 + s3);
        if (kq) part[kq - 1][d] = ps;
        __syncthreads();
        if (kq == 0) {
            float tot = ps + part[0][d] + part[1][d] + part[2][d] + wb;
            acc = fmaf(d_w[b * TT + t], tanhf(tot), acc);
        }
        if (havenext && tid < DIM) e_s[cur ^ 1][tid] = enext;
        __syncthreads();
        cur ^= 1;
    }
    if (kq == 0) atomicAdd(&d_hT[b * DIM + dg], acc);
}

// ---------------------------------------------------------------------------
// K4: out[b,v] = sum_k hT[b,k] * head_w[v,k] + head_b[v]
// Block: 256 v x 64 b (all b), 256 threads, 8v x 8b register tile per thread.
// smem: hTs[k][b] (64KB, loaded once) + hw tile [16][260] streamed.
// ---------------------------------------------------------------------------
#define HWS_STRIDE 260
#define SMEM_HEAD ((DIM * 64 + 16 * HWS_STRIDE) * 4)

__global__ void __launch_bounds__(256, 1) k_head(
        const float* __restrict__ hw, const float* __restrict__ hb,
        float* __restrict__ out) {
    extern __shared__ float smem[];
    float* hTs = smem;                 // [DIM][64]
    float* hws = smem + DIM * 64;      // [16][HWS_STRIDE]

    int tid = threadIdx.x;
    int vbase = blockIdx.x * 256;
    int v0l = (tid & 31) * 8;
    int b0 = (tid >> 5) * 8;

    // load hT transposed: hTs[k][b]
    for (int i = tid; i < DIM * 64; i += 256) {
        int k = i >> 6, bb = i & 63;
        hTs[k * 64 + bb] = d_hT[bb * DIM + k];
    }
    __syncthreads();

    float acc[8][8];
#pragma unroll
    for (int vi = 0; vi < 8; vi++)
#pragma unroll
        for (int bi = 0; bi < 8; bi++) acc[vi][bi] = 0.f;

    for (int kt = 0; kt < 16; kt++) {
        int kb = kt * 16;
        // cooperative load of head_w tile: 256 v x 16 k -> hws[kk][v]
#pragma unroll
        for (int r = 0; r < 16; r++) {
            int idx = r * 256 + tid;
            int vl = idx >> 4, kk = idx & 15;
            hws[kk * HWS_STRIDE + vl] =
                hw[(size_t)(vbase + vl) * DIM + kb + kk];
        }
        __syncthreads();
#pragma unroll
        for (int kk = 0; kk < 16; kk++) {
            int k = kb + kk;
            float4 hA = *(const float4*)&hws[kk * HWS_STRIDE + v0l];
            float4 hB = *(const float4*)&hws[kk * HWS_STRIDE + v0l + 4];
            float4 tA = *(const float4*)&hTs[k * 64 + b0];
            float4 tB = *(const float4*)&hTs[k * 64 + b0 + 4];
            float hv[8] = {hA.x, hA.y, hA.z, hA.w, hB.x, hB.y, hB.z, hB.w};
            float tv[8] = {tA.x, tA.y, tA.z, tA.w, tB.x, tB.y, tB.z, tB.w};
#pragma unroll
            for (int vi = 0; vi < 8; vi++)
#pragma unroll
                for (int bi = 0; bi < 8; bi++)
                    acc[vi][bi] = fmaf(hv[vi], tv[bi], acc[vi][bi]);
        }
        __syncthreads();
    }

#pragma unroll
    for (int vi = 0; vi < 8; vi++) {
        int v = vbase + v0l + vi;
        float bias = hb[v];
#pragma unroll
        for (int bi = 0; bi < 8; bi++)
            out[(size_t)(b0 + bi) * VOCAB + v] = acc[vi][bi] + bias;
    }
}

// ---------------------------------------------------------------------------
extern "C" void kernel_launch(void* const* d_in, const int* in_sizes, int n_in,
                              void* d_out, int out_size) {
    const int*   x      = (const int*)d_in[0];
    const float* emb    = (const float*)d_in[1];
    const float* W_w    = (const float*)d_in[2];
    const float* W_b    = (const float*)d_in[3];
    const float* Wg_w   = (const float*)d_in[4];
    const float* Wg_b   = (const float*)d_in[5];
    const float* head_w = (const float*)d_in[6];
    const float* head_b = (const float*)d_in[7];
    float* out = (float*)d_out;

    k_vocab_gate<<<(VOCAB + 7) / 8, 256>>>(emb, Wg_w);
    k_scan<<<BB, 256>>>(x, Wg_b);
    dim3 g3(2, NT, BB);
    k_main<<<g3, 512>>>(x, emb, W_w, W_b);
    cudaFuncSetAttribute(k_head, cudaFuncAttributeMaxDynamicSharedMemorySize,
                         SMEM_HEAD);
    k_head<<<VOCAB / 256, 256, SMEM_HEAD>>>(head_w, head_b, out);
}

// round 2
// speedup vs baseline: 1.1194x; 1.1194x over previous
#include <cuda_runtime.h>
#include <cuda_bf16.h>
#include <math.h>

#define BB 64
#define TT 2048
#define DIM 256
#define VOCAB 32000
#define NT 2
#define EPS_CUT 1e-9f

// Scratch (static __device__ globals: no allocation)
__device__ float d_p[VOCAB];      // emb[v] . Wg
__device__ float d_w[BB * TT];    // per-step weight (1-g)*suffixprod
__device__ int   d_t0[BB];        // cutoff index per batch
__device__ float d_hT[BB * DIM];  // final hidden state
__device__ __nv_bfloat16 d_hThi[BB * DIM];  // hT split high
__device__ __nv_bfloat16 d_hTlo[BB * DIM];  // hT split low

// ---------------------------------------------------------------------------
// K1: p[v] = dot(emb[v], Wg)   (one warp per vocab row)
// ---------------------------------------------------------------------------
__global__ void k_vocab_gate(const float* __restrict__ emb,
                             const float* __restrict__ Wg) {
    int warp = (blockIdx.x * blockDim.x + threadIdx.x) >> 5;
    int lane = threadIdx.x & 31;
    if (warp >= VOCAB) return;
    const float4* e4 = (const float4*)(emb + (size_t)warp * DIM);
    const float4* w4 = (const float4*)Wg;
    float4 a0 = e4[lane], a1 = e4[lane + 32];
    float4 b0 = w4[lane], b1 = w4[lane + 32];
    float s = a0.x * b0.x + a0.y * b0.y + a0.z * b0.z + a0.w * b0.w
            + a1.x * b1.x + a1.y * b1.y + a1.z * b1.z + a1.w * b1.w;
#pragma unroll
    for (int off = 16; off; off >>= 1)
        s += __shfl_xor_sync(0xffffffffu, s, off);
    if (lane == 0) d_p[warp] = s;
}

// ---------------------------------------------------------------------------
// K2: per-batch suffix-product scan (unchanged)
// ---------------------------------------------------------------------------
__global__ void k_scan(const int* __restrict__ x,
                       const float* __restrict__ Wg_b) {
    int b = blockIdx.x;
    int tid = threadIdx.x;
    float gb = Wg_b[0];

    __shared__ float sm[256];
    __shared__ int s_t0;
    if (tid == 0) s_t0 = TT;

    float gl[8], sl[8];
    int tb = tid * 8;
    float cum = 1.f;
#pragma unroll
    for (int j = 7; j >= 0; j--) {
        int xv = x[b * TT + tb + j];
        float z = d_p[xv] + gb;
        float g = 1.f / (1.f + expf(-z));
        gl[j] = g;
        sl[j] = cum;
        cum *= g;
    }
    sm[tid] = cum;
    __syncthreads();
#pragma unroll
    for (int off = 1; off < 256; off <<= 1) {
        float v = (tid + off < 256) ? sm[tid + off] : 1.f;
        __syncthreads();
        sm[tid] *= v;
        __syncthreads();
    }
    float Q = (tid < 255) ? sm[tid + 1] : 1.f;

    int myt0 = TT;
#pragma unroll
    for (int j = 0; j < 8; j++) {
        float S = Q * sl[j];
        d_w[b * TT + tb + j] = (1.f - gl[j]) * S;
        int t = tb + j;
        if (S >= EPS_CUT && t < myt0) myt0 = t;
    }
    atomicMin(&s_t0, myt0);
    d_hT[b * DIM + tid] = 0.f;
    __syncthreads();
    if (tid == 0) d_t0[b] = s_t0;
}

// ---------------------------------------------------------------------------
// K3: hT[b,:] += sum_{t>=t0} w_t * tanh(W @ emb[x[b,t]] + Wb)  (unchanged)
// ---------------------------------------------------------------------------
__global__ void __launch_bounds__(512, 2) k_main(
        const int* __restrict__ x, const float* __restrict__ emb,
        const float* __restrict__ W, const float* __restrict__ Wb) {
    int dh = blockIdx.x;
    int chunk = blockIdx.y;
    int b = blockIdx.z;
    int tid = threadIdx.x;
    int d = tid & 127;
    int kq = tid >> 7;
    int dg = dh * 128 + d;

    float wreg[64];
    const float4* W4 = (const float4*)(W + (size_t)dg * DIM + kq * 64);
#pragma unroll
    for (int i = 0; i < 16; i++) {
        float4 v = W4[i];
        wreg[4 * i + 0] = v.x; wreg[4 * i + 1] = v.y;
        wreg[4 * i + 2] = v.z; wreg[4 * i + 3] = v.w;
    }
    float wb = Wb[dg];
    int t0 = d_t0[b];

    __shared__ float e_s[2][DIM];
    __shared__ float part[3][128];

    float acc = 0.f;
    int tstart = TT - 1 - chunk;
    int cur = 0;
    if (tstart >= t0 && tid < DIM) {
        int xv = x[b * TT + tstart];
        e_s[0][tid] = emb[(size_t)xv * DIM + tid];
    }
    __syncthreads();

    for (int t = tstart; t >= t0; t -= NT) {
        float enext = 0.f;
        int tn = t - NT;
        bool havenext = (tn >= t0);
        if (havenext && tid < DIM) {
            int xv = x[b * TT + tn];
            enext = emb[(size_t)xv * DIM + tid];
        }
        const float4* ev = (const float4*)(&e_s[cur][kq * 64]);
        float s0 = 0.f, s1 = 0.f, s2 = 0.f, s3 = 0.f;
#pragma unroll
        for (int i = 0; i < 16; i++) {
            float4 e4 = ev[i];
            s0 = fmaf(wreg[4 * i + 0], e4.x, s0);
            s1 = fmaf(wreg[4 * i + 1], e4.y, s1);
            s2 = fmaf(wreg[4 * i + 2], e4.z, s2);
            s3 = fmaf(wreg[4 * i + 3], e4.w, s3);
        }
        float ps = (s0 + s1) + (s2 + s3);
        if (kq) part[kq - 1][d] = ps;
        __syncthreads();
        if (kq == 0) {
            float tot = ps + part[0][d] + part[1][d] + part[2][d] + wb;
            acc = fmaf(d_w[b * TT + t], tanhf(tot), acc);
        }
        if (havenext && tid < DIM) e_s[cur ^ 1][tid] = enext;
        __syncthreads();
        cur ^= 1;
    }
    if (kq == 0) atomicAdd(&d_hT[b * DIM + dg], acc);
}

// ---------------------------------------------------------------------------
// K3b: split hT into bf16 hi/lo for the tensor-core head GEMM
// ---------------------------------------------------------------------------
__global__ void k_prep() {
    int i = blockIdx.x * 256 + threadIdx.x;
    float v = d_hT[i];
    __nv_bfloat16 h = __float2bfloat16_rn(v);
    d_hThi[i] = h;
    d_hTlo[i] = __float2bfloat16_rn(v - __bfloat162float(h));
}

// ---------------------------------------------------------------------------
// K4: out[b,v] = hT @ head_w^T + head_b via bf16-split mma.sync (tensor pipe)
//   out = Ahi*Bhi + Ahi*Blo + Alo*Bhi  (fp32 accum; lo*lo dropped, ~2^-16)
// Grid: 125 blocks x 256 thr (8 warps). Block tile: M=64(all b) x N=256 v.
// Warp tile: 64 x 32 -> 4 m-tiles x 4 n-tiles of m16n8k16, K chunked by 16.
// head_w fp32 loaded cooperatively, converted to bf16 hi/lo in smem
// (double-buffered). A (hT hi/lo, 32KB total) read from global via L1.
// ---------------------------------------------------------------------------
__device__ __forceinline__ void mma_bf16(float* d, const unsigned* a,
                                         const unsigned* b) {
    asm volatile(
        "mma.sync.aligned.m16n8k16.row.col.f32.bf16.bf16.f32 "
        "{%0,%1,%2,%3},{%4,%5,%6,%7},{%8,%9},{%0,%1,%2,%3};\n"
        : "+f"(d[0]), "+f"(d[1]), "+f"(d[2]), "+f"(d[3])
        : "r"(a[0]), "r"(a[1]), "r"(a[2]), "r"(a[3]), "r"(b[0]), "r"(b[1]));
}

__global__ void __launch_bounds__(256, 1) k_head_tc(
        const float* __restrict__ hw, const float* __restrict__ hb,
        float* __restrict__ out) {
    // [stage][hi/lo][v=256][kpair=8] as packed bf16x2 words
    __shared__ unsigned sB[2][2][256 * 8];

    int tid = threadIdx.x;
    int w = tid >> 5;          // warp 0..7
    int lane = tid & 31;
    int g = lane >> 2;         // group id 0..7
    int tig = lane & 3;        // thread in group
    int vbase = blockIdx.x * 256;

    float acc[4][4][4];
#pragma unroll
    for (int mt = 0; mt < 4; mt++)
#pragma unroll
        for (int nt = 0; nt < 4; nt++)
#pragma unroll
            for (int r = 0; r < 4; r++) acc[mt][nt][r] = 0.f;

    const unsigned* Ah = (const unsigned*)d_hThi;  // [64][128] words
    const unsigned* Al = (const unsigned*)d_hTlo;

    // ---- load stage 0 (kc = 0) ----
    {
#pragma unroll
        for (int r = 0; r < 8; r++) {
            int idx = r * 256 + tid;
            int vl = idx >> 3, kp = idx & 7;
            float2 f = *(const float2*)&hw[(size_t)(vbase + vl) * DIM + kp * 2];
            __nv_bfloat162 h2 = __float22bfloat162_rn(f);
            float2 rr;
            rr.x = f.x - __bfloat162float(h2.x);
            rr.y = f.y - __bfloat162float(h2.y);
            __nv_bfloat162 l2 = __float22bfloat162_rn(rr);
            sB[0][0][vl * 8 + kp] = *(unsigned*)&h2;
            sB[0][1][vl * 8 + kp] = *(unsigned*)&l2;
        }
    }
    __syncthreads();

    int cur = 0;
    for (int kc = 0; kc < 16; kc++) {
        // prefetch next k-chunk of head_w into registers
        float2 pf[8];
        if (kc < 15) {
            int kb = (kc + 1) * 16;
#pragma unroll
            for (int r = 0; r < 8; r++) {
                int idx = r * 256 + tid;
                int vl = idx >> 3, kp = idx & 7;
                pf[r] = *(const float2*)&hw[(size_t)(vbase + vl) * DIM + kb + kp * 2];
            }
        }

        // A fragments for this k-chunk (global, L1-resident)
        unsigned ahi[4][4], alo[4][4];
#pragma unroll
        for (int mt = 0; mt < 4; mt++) {
            int r0 = (mt * 16 + g) * 128 + kc * 8 + tig;
            int r1 = (mt * 16 + g + 8) * 128 + kc * 8 + tig;
            ahi[mt][0] = Ah[r0];     ahi[mt][1] = Ah[r1];
            ahi[mt][2] = Ah[r0 + 4]; ahi[mt][3] = Ah[r1 + 4];
            alo[mt][0] = Al[r0];     alo[mt][1] = Al[r1];
            alo[mt][2] = Al[r0 + 4]; alo[mt][3] = Al[r1 + 4];
        }

#pragma unroll
        for (int nt = 0; nt < 4; nt++) {
            int v = w * 32 + nt * 8 + g;   // local v for this B column
            unsigned bh[2], bl[2];
            bh[0] = sB[cur][0][v * 8 + tig];
            bh[1] = sB[cur][0][v * 8 + tig + 4];
            bl[0] = sB[cur][1][v * 8 + tig];
            bl[1] = sB[cur][1][v * 8 + tig + 4];
#pragma unroll
            for (int mt = 0; mt < 4; mt++) {
                mma_bf16(acc[mt][nt], ahi[mt], bh);
                mma_bf16(acc[mt][nt], ahi[mt], bl);
                mma_bf16(acc[mt][nt], alo[mt], bh);
            }
        }
        __syncthreads();
        if (kc < 15) {
#pragma unroll
            for (int r = 0; r < 8; r++) {
                int idx = r * 256 + tid;
                int vl = idx >> 3, kp = idx & 7;
                float2 f = pf[r];
                __nv_bfloat162 h2 = __float22bfloat162_rn(f);
                float2 rr;
                rr.x = f.x - __bfloat162float(h2.x);
                rr.y = f.y - __bfloat162float(h2.y);
                __nv_bfloat162 l2 = __float22bfloat162_rn(rr);
                sB[cur ^ 1][0][vl * 8 + kp] = *(unsigned*)&h2;
                sB[cur ^ 1][1][vl * 8 + kp] = *(unsigned*)&l2;
            }
            __syncthreads();
        }
        cur ^= 1;
    }

    // epilogue: add bias, write out [b, VOCAB]
#pragma unroll
    for (int nt = 0; nt < 4; nt++) {
        int v = vbase + w * 32 + nt * 8 + tig * 2;
        float2 bias = *(const float2*)&hb[v];
#pragma unroll
        for (int mt = 0; mt < 4; mt++) {
            int b0r = mt * 16 + g;
            float2 o0, o1;
            o0.x = acc[mt][nt][0] + bias.x;
            o0.y = acc[mt][nt][1] + bias.y;
            o1.x = acc[mt][nt][2] + bias.x;
            o1.y = acc[mt][nt][3] + bias.y;
            *(float2*)&out[(size_t)b0r * VOCAB + v] = o0;
            *(float2*)&out[(size_t)(b0r + 8) * VOCAB + v] = o1;
        }
    }
}

// ---------------------------------------------------------------------------
extern "C" void kernel_launch(void* const* d_in, const int* in_sizes, int n_in,
                              void* d_out, int out_size) {
    const int*   x      = (const int*)d_in[0];
    const float* emb    = (const float*)d_in[1];
    const float* W_w    = (const float*)d_in[2];
    const float* W_b    = (const float*)d_in[3];
    const float* Wg_w   = (const float*)d_in[4];
    const float* Wg_b   = (const float*)d_in[5];
    const float* head_w = (const float*)d_in[6];
    const float* head_b = (const float*)d_in[7];
    float* out = (float*)d_out;

    k_vocab_gate<<<(VOCAB + 7) / 8, 256>>>(emb, Wg_w);
    k_scan<<<BB, 256>>>(x, Wg_b);
    dim3 g3(2, NT, BB);
    k_main<<<g3, 512>>>(x, emb, W_w, W_b);
    k_prep<<<BB, 256>>>();
    k_head_tc<<<VOCAB / 256, 256>>>(head_w, head_b, out);
}